// round 15
// baseline (speedup 1.0000x reference)
#include <cuda_runtime.h>
#include <cuda_fp16.h>
#include <cuda_bf16.h>

// Problem constants
#define BB   64
#define SS   1024
#define II   512
#define HH   512
#define NG3  1536          // 3*H
#define NWORK 96           // 3 classes x 32 working CTAs
#define NGRID 192          // padded grid (dummies exit immediately)
#define THR  256           // 8 warps: n-split (nh = warp>>2 picks 3 of 6 nf)
#define BWORDS 12288       // B_perm fp16x2 words (48 KB)
#define SCAN_SMEM 131072   // request > 113KB -> 1 CTA/SM guaranteed

// ---------------- static device scratch --------------------------------------
__device__ float g_xs1[(long)SS * BB * NG3];     // layer-1 input projections
__device__ unsigned g_h1p16[16][BB * HH / 2];    // fp16x2 h1 ring (fragment-perm)
__device__ unsigned g_h2p16[2][BB * HH / 2];     // fp16x2 h2 pingpong (perm)
__device__ float g_xg2r[16][BB * NG3];           // layer-2 input projection ring
__device__ float g_gb1[BB * NG3];
__device__ float g_gb2[BB * NG3];
__device__ float g_h1b[BB * HH];
__device__ float g_fcin[BB * 2 * HH];            // [b][fwd H | bwd H]

__device__ unsigned g_flg[3][32];                // per-class per-CTA progress flags

// ---------------- helpers ----------------------------------------------------
__device__ __forceinline__ unsigned f2tf(float f) {
    unsigned u;
    asm("cvt.rna.tf32.f32 %0, %1;" : "=r"(u) : "f"(f));
    return u;
}

__device__ __forceinline__ unsigned packh2(float lo, float hi) {
    __half2 h = __floats2half2_rn(lo, hi);
    return *(unsigned*)&h;
}

// fp16 MMA: D[16x8] += A[16x16] * B[16x8], fp32 accum
__device__ __forceinline__ void mmah(float c[4], const unsigned a[4], unsigned b0, unsigned b1) {
    asm volatile(
        "mma.sync.aligned.m16n8k16.row.col.f32.f16.f16.f32 "
        "{%0,%1,%2,%3},{%4,%5,%6,%7},{%8,%9},{%0,%1,%2,%3};"
        : "+f"(c[0]), "+f"(c[1]), "+f"(c[2]), "+f"(c[3])
        : "r"(a[0]), "r"(a[1]), "r"(a[2]), "r"(a[3]), "r"(b0), "r"(b1));
}

// tf32 MMA (non-scan kernels)
__device__ __forceinline__ void mma8(float c[4], const unsigned a[4], unsigned b0, unsigned b1) {
    asm volatile(
        "mma.sync.aligned.m16n8k8.row.col.f32.tf32.tf32.f32 "
        "{%0,%1,%2,%3},{%4,%5,%6,%7},{%8,%9},{%0,%1,%2,%3};"
        : "+f"(c[0]), "+f"(c[1]), "+f"(c[2]), "+f"(c[3])
        : "r"(a[0]), "r"(a[1]), "r"(a[2]), "r"(a[3]), "r"(b0), "r"(b1));
}

__device__ __forceinline__ float sigm(float v) { return 1.f / (1.f + __expf(-v)); }
__device__ __forceinline__ float tanh_fast(float v) {
    return 1.f - 2.f / (1.f + __expf(2.f * v));
}

// fused dual-array wait: one poll round checks fA[lane]>=tA (and fB[lane]>=tB)
__device__ __forceinline__ void wait_fused(const unsigned* fA, unsigned tA,
                                           const unsigned* fB, unsigned tB, bool useB) {
    if (threadIdx.x < 32) {
        bool done = false;
        while (!done) {
            unsigned v;
            asm volatile("ld.acquire.gpu.u32 %0, [%1];"
                         : "=r"(v) : "l"(fA + threadIdx.x) : "memory");
            bool ok = (v >= tA);
            if (useB) {
                unsigned w;
                asm volatile("ld.acquire.gpu.u32 %0, [%1];"
                             : "=r"(w) : "l"(fB + threadIdx.x) : "memory");
                ok = ok && (w >= tB);
            }
            done = __all_sync(0xFFFFFFFFu, ok);
        }
    }
    __syncthreads();
}

// B2 wait: own class (lane-indexed) + single xg2 producer flag, one round
__device__ __forceinline__ void wait_b2(const unsigned* fown, unsigned town,
                                        const unsigned* fxg, unsigned txg) {
    if (threadIdx.x < 32) {
        bool done = false;
        while (!done) {
            unsigned v, w;
            asm volatile("ld.acquire.gpu.u32 %0, [%1];"
                         : "=r"(v) : "l"(fown + threadIdx.x) : "memory");
            asm volatile("ld.acquire.gpu.u32 %0, [%1];"
                         : "=r"(w) : "l"(fxg) : "memory");
            done = __all_sync(0xFFFFFFFFu, (v >= town) && (w >= txg));
        }
    }
    __syncthreads();
}

// publish own progress flag (release)
__device__ __forceinline__ void publish(unsigned* flag, unsigned target) {
    __syncthreads();
    if (threadIdx.x == 0) {
        __threadfence();
        asm volatile("st.release.gpu.u32 [%0], %1;" :: "l"(flag), "r"(target) : "memory");
    }
}

// ---------------- 64x64 TF32 GEMM core (non-scan kernels) --------------------
__device__ __forceinline__ void gemm_core(const float* __restrict__ A, long lda,
                                          const float* __restrict__ B512, int K,
                                          const float* __restrict__ bias,
                                          float* __restrict__ C, int ldc)
{
    __shared__ unsigned As[64][33];
    __shared__ unsigned Bs[32][65];

    const int tid  = threadIdx.x;
    const int lane = tid & 31;
    const int warp = tid >> 5;
    const int wm = warp >> 1, wn = warp & 1;
    const int g = lane >> 2, t = lane & 3;

    float acc[2][4][4];
#pragma unroll
    for (int a = 0; a < 2; a++)
#pragma unroll
        for (int b = 0; b < 4; b++)
#pragma unroll
            for (int c = 0; c < 4; c++) acc[a][b][c] = 0.f;

    float4 ra[4], rbv[4];
#pragma unroll
    for (int i = 0; i < 4; i++) {
        int f = tid + i * 128;
        ra[i]  = *(const float4*)(A + (long)(f >> 3) * lda + ((f & 7) << 2));
        rbv[i] = *(const float4*)(B512 + (long)(f >> 4) * 512 + ((f & 15) << 2));
    }

    for (int kc = 0; kc < K; kc += 32) {
#pragma unroll
        for (int i = 0; i < 4; i++) {
            int f = tid + i * 128;
            int r = f >> 3, cc = (f & 7) << 2;
            As[r][cc + 0] = f2tf(ra[i].x);
            As[r][cc + 1] = f2tf(ra[i].y);
            As[r][cc + 2] = f2tf(ra[i].z);
            As[r][cc + 3] = f2tf(ra[i].w);
            int bk = f >> 4, bc = (f & 15) << 2;
            Bs[bk][bc + 0] = f2tf(rbv[i].x);
            Bs[bk][bc + 1] = f2tf(rbv[i].y);
            Bs[bk][bc + 2] = f2tf(rbv[i].z);
            Bs[bk][bc + 3] = f2tf(rbv[i].w);
        }
        __syncthreads();

        if (kc + 32 < K) {
#pragma unroll
            for (int i = 0; i < 4; i++) {
                int f = tid + i * 128;
                ra[i]  = *(const float4*)(A + (long)(f >> 3) * lda + (kc + 32) + ((f & 7) << 2));
                rbv[i] = *(const float4*)(B512 + (long)(kc + 32 + (f >> 4)) * 512 + ((f & 15) << 2));
            }
        }

#pragma unroll
        for (int ks = 0; ks < 4; ks++) {
            int kb = ks * 8;
            unsigned afr[2][4];
#pragma unroll
            for (int mf = 0; mf < 2; mf++) {
                int rb_ = wm * 32 + mf * 16;
                afr[mf][0] = As[rb_ + g][kb + t];
                afr[mf][1] = As[rb_ + 8 + g][kb + t];
                afr[mf][2] = As[rb_ + g][kb + 4 + t];
                afr[mf][3] = As[rb_ + 8 + g][kb + 4 + t];
            }
#pragma unroll
            for (int nf = 0; nf < 4; nf++) {
                int cb = wn * 32 + nf * 8;
                unsigned b0 = Bs[kb + t][cb + g];
                unsigned b1 = Bs[kb + 4 + t][cb + g];
                mma8(acc[0][nf], afr[0], b0, b1);
                mma8(acc[1][nf], afr[1], b0, b1);
            }
        }
        __syncthreads();
    }

#pragma unroll
    for (int mf = 0; mf < 2; mf++)
#pragma unroll
        for (int nf = 0; nf < 4; nf++) {
            int row = wm * 32 + mf * 16 + g;
            int col = wn * 32 + nf * 8 + t * 2;
            float b0v = bias ? bias[col] : 0.f;
            float b1v = bias ? bias[col + 1] : 0.f;
            C[(long)row * ldc + col]           = acc[mf][nf][0] + b0v;
            C[(long)row * ldc + col + 1]       = acc[mf][nf][1] + b1v;
            C[(long)(row + 8) * ldc + col]     = acc[mf][nf][2] + b0v;
            C[(long)(row + 8) * ldc + col + 1] = acc[mf][nf][3] + b1v;
        }
}

// ---------------- kernels -----------------------------------------------------

__global__ void k_zero() {
    long n = BB * HH / 2;
    for (long i = blockIdx.x * blockDim.x + threadIdx.x; i < n; i += (long)gridDim.x * blockDim.x) {
        g_h1p16[0][i] = 0u;
        g_h2p16[0][i] = 0u;
    }
    if (blockIdx.x == 0 && threadIdx.x < 96)
        g_flg[threadIdx.x >> 5][threadIdx.x & 31] = 0;
}

// xs1[s][b][n] = x[b][s][:] @ Wi[0][0][gate] + b[0][0]
__global__ __launch_bounds__(128) void k_proj(const float* __restrict__ x,
                                              const float* __restrict__ Wi,
                                              const float* __restrict__ bv)
{
    int n = blockIdx.x * 64;
    int s = blockIdx.y;
    int gate = n >> 9, cig = n & 511;
    const float* A = x + (long)s * II;
    const float* B512 = Wi + ((long)(0 * 3 + gate)) * 512 * 512 + cig;   // Wi[0][0]
    gemm_core(A, (long)SS * II, B512, 512, bv + n,
              g_xs1 + ((long)s * BB) * NG3 + n, NG3);
}

// ---------------- persistent scan kernel (FP16 MMA, n-split, fused waits) -----
// 96 working CTAs x 256 threads (8 warps). warp = nh*4 + wg.
// Rings widened to 16; slack checks folded into the main wait and done only
// every 4th iteration; B2 waits on a single B1 flag; A-prefetch depth 16.
//   A  (0-31):  Wh1 over h1(it)   -> EW L1 -> h1(it+1) ring[16]
//   B1 (32-63): Wi2 over h1(it+1) -> xg2[it] ring[16]
//   B2 (64-95): Wh2 over h2(it) + EW L2 (xg2[it]) -> h2(it+1)
__global__ void __launch_bounds__(THR, 1) k_scan(const float* __restrict__ Wi,
                                                 const float* __restrict__ Wh,
                                                 const float* __restrict__ bv)
{
    extern __shared__ unsigned smemu[];
    unsigned* Bsm = smemu;               // B_perm fp16x2 (48 KB)

    const int tid  = threadIdx.x;
    const int lane = tid & 31;
    const int warp = tid >> 5;           // 0..7
    const int wg   = warp & 3;           // row group
    const int nh   = warp >> 2;          // nf half == u half
    const int g = lane >> 2, t = lane & 3;
    const int ct = blockIdx.x;
    if (ct >= NWORK) return;             // grid padding
    const int cls = ct >> 5;             // 0=A, 1=B1, 2=B2
    const int ci  = ct & 31;
    const int u0  = ci * 16;

    // ---- one-time weight stage into B_perm (fp16x2); nf = uh*3 + gate ----
    const float* Wbase = (cls == 0) ? Wh : (cls == 1) ? (Wi + 6L * 262144)
                                                      : (Wh + 6L * 262144);
    for (int widx = tid; widx < BWORDS; widx += THR) {
        int reg = widx & 1;
        int lane2 = (widx >> 1) & 31;
        int m = widx >> 6;               // c*6 + nf
        int nf = m % 6, c = m / 6;
        int g2 = lane2 >> 2, t2 = lane2 & 3;
        int kk = c * 16 + reg * 8 + t2 * 2;
        int gate = nf % 3, uh = nf / 3;
        int col = u0 + uh * 8 + g2;
        const float* Wg = Wbase + (long)gate * 262144;
        Bsm[widx] = packh2(Wg[(long)kk * 512 + col], Wg[(long)(kk + 1) * 512 + col]);
    }

    // layer-2 bias prefetch (b[1][0]) for B2, this warp's u-half
    const float* b2 = bv + 2 * NG3;
    float b2r[2], b2z[2], b2n[2];
    if (cls == 2) {
#pragma unroll
        for (int jl = 0; jl < 2; jl++) {
            int u = u0 + nh * 8 + t * 2 + jl;
            b2r[jl] = __ldg(b2 + u);
            b2z[jl] = __ldg(b2 + 512 + u);
            b2n[jl] = __ldg(b2 + 1024 + u);
        }
    }

    float hreg[2][2];                    // own h cells [j2][jl] (this warp's u-half)
#pragma unroll
    for (int a = 0; a < 2; a++)
#pragma unroll
        for (int b = 0; b < 2; b++) hreg[a][b] = 0.f;

    __syncthreads();                     // B_perm ready

    for (int it = 0; it < SS; it++) {
        // ---- fused top waits (one poll round; slack checked every 4th it) ----
        const bool chk = (it >= 8) && ((it & 3) == 0);
        const unsigned* hp;
        if (cls == 0) {
            wait_fused(g_flg[0], (unsigned)it, g_flg[1], (unsigned)(it - 7), chk);
            hp = g_h1p16[it & 15];
        } else if (cls == 1) {
            wait_fused(g_flg[0], (unsigned)(it + 1), g_flg[2], (unsigned)(it - 7), chk);
            hp = g_h1p16[(it + 1) & 15];
        } else {
            wait_b2(g_flg[2], (unsigned)it, &g_flg[1][ci], (unsigned)(it + 1));
            hp = g_h2p16[it & 1];
        }

        // ---- A-operand prefetch FIRST (critical path), depth 16 ----
        const uint4* gA = (const uint4*)hp + wg * 32 + lane;
        uint4 areg[16];
#pragma unroll
        for (int j = 0; j < 16; j++) areg[j] = __ldcg(gA + j * 128);

        // EW operand prefetch (this warp's u-half; consumed after GEMM)
        float pf_x[2][2][3];             // [j2][jl][gate]
        if (cls == 0) {
#pragma unroll
            for (int j2 = 0; j2 < 2; j2++) {
                int b = wg * 16 + g + 8 * j2;
                const float* xs = g_xs1 + ((long)it * BB + b) * NG3;
#pragma unroll
                for (int jl = 0; jl < 2; jl++) {
                    int u = u0 + nh * 8 + t * 2 + jl;
                    pf_x[j2][jl][0] = __ldcg(xs + u);
                    pf_x[j2][jl][1] = __ldcg(xs + 512 + u);
                    pf_x[j2][jl][2] = __ldcg(xs + 1024 + u);
                }
            }
        } else if (cls == 2) {
            const float* xg = g_xg2r[it & 15];
#pragma unroll
            for (int j2 = 0; j2 < 2; j2++) {
                int b = wg * 16 + g + 8 * j2;
#pragma unroll
                for (int jl = 0; jl < 2; jl++) {
                    int u = u0 + nh * 8 + t * 2 + jl;
                    pf_x[j2][jl][0] = __ldcg(xg + b * NG3 + u);
                    pf_x[j2][jl][1] = __ldcg(xg + b * NG3 + 512 + u);
                    pf_x[j2][jl][2] = __ldcg(xg + b * NG3 + 1024 + u);
                }
            }
        }

        // ---- GEMM: 32 k16-chunks, 3 nf frags, 16-deep rolling prefetch ----
        float acc[3][4];
#pragma unroll
        for (int f = 0; f < 3; f++)
#pragma unroll
            for (int c = 0; c < 4; c++) acc[f][c] = 0.f;

#pragma unroll 8
        for (int c = 0; c < 32; c++) {
            unsigned a[4] = {areg[c & 15].x, areg[c & 15].y,
                             areg[c & 15].z, areg[c & 15].w};
            if (c + 16 < 32) areg[c & 15] = __ldcg(gA + (c + 16) * 128);
            const unsigned* Bp = Bsm + c * 384 + (nh * 3) * 64 + lane * 2;
#pragma unroll
            for (int f = 0; f < 3; f++) {
                uint2 bb = *(const uint2*)(Bp + f * 64);
                mmah(acc[f], a, bb.x, bb.y);
            }
        }

        // ---- class-specific epilogue (this warp's u-half) ----
        if (cls == 0) {
            unsigned* hout = g_h1p16[(it + 1) & 15];
            unsigned base = ((unsigned)(ci * 4 + wg) * 32 + lane) * 4;
#pragma unroll
            for (int j2 = 0; j2 < 2; j2++) {
                float v2[2];
#pragma unroll
                for (int jl = 0; jl < 2; jl++) {
                    int c = j2 * 2 + jl;
                    float r  = sigm(pf_x[j2][jl][0] + acc[0][c]);
                    float z  = sigm(pf_x[j2][jl][1] + acc[1][c]);
                    float nn = tanh_fast(pf_x[j2][jl][2] + r * acc[2][c]);
                    float v  = (1.f - z) * nn + z * hreg[j2][jl];
                    hreg[j2][jl] = v;
                    v2[jl] = v;
                }
                __stcg(&hout[base + j2 + 2 * nh], packh2(v2[0], v2[1]));
            }
        } else if (cls == 1) {
            float* xg = g_xg2r[it & 15];
#pragma unroll
            for (int gate = 0; gate < 3; gate++)
#pragma unroll
                for (int j2 = 0; j2 < 2; j2++) {
                    int b = wg * 16 + g + 8 * j2;
                    float2 val = make_float2(acc[gate][j2 * 2], acc[gate][j2 * 2 + 1]);
                    __stcg((float2*)(xg + b * NG3 + gate * 512 + u0 + nh * 8 + t * 2), val);
                }
        } else {
            unsigned* hout = g_h2p16[(it + 1) & 1];
            unsigned base = ((unsigned)(ci * 4 + wg) * 32 + lane) * 4;
#pragma unroll
            for (int j2 = 0; j2 < 2; j2++) {
                int b = wg * 16 + g + 8 * j2;
                float v2[2];
#pragma unroll
                for (int jl = 0; jl < 2; jl++) {
                    int u = u0 + nh * 8 + t * 2 + jl;
                    int c = j2 * 2 + jl;
                    float xr = pf_x[j2][jl][0] + b2r[jl];
                    float xz = pf_x[j2][jl][1] + b2z[jl];
                    float xn = pf_x[j2][jl][2] + b2n[jl];
                    float r2 = sigm(xr + acc[0][c]);
                    float z2 = sigm(xz + acc[1][c]);
                    float n2 = tanh_fast(xn + r2 * acc[2][c]);
                    float v  = (1.f - z2) * n2 + z2 * hreg[j2][jl];
                    hreg[j2][jl] = v;
                    v2[jl] = v;
                    if (it == SS - 1) __stcg(&g_fcin[b * (2 * HH) + u], v);
                }
                __stcg(&hout[base + j2 + 2 * nh], packh2(v2[0], v2[1]));
            }
        }

        publish(&g_flg[cls][ci], (unsigned)(it + 1));
    }
}

// backward step 1 projection: x[:,1023,:] @ Wi[0][1] + b[0][1]
__global__ __launch_bounds__(128) void k_gb1(const float* __restrict__ x,
                                             const float* __restrict__ Wi,
                                             const float* __restrict__ bv)
{
    int n = blockIdx.x * 64;
    int gate = n >> 9, cig = n & 511;
    const float* A = x + (long)(SS - 1) * II;
    const float* B512 = Wi + ((long)(1 * 3 + gate)) * 512 * 512 + cig;   // Wi[0][1]
    gemm_core(A, (long)SS * II, B512, 512, bv + 1 * NG3 + n, g_gb1 + n, NG3);
}

__global__ void k_ewb1()
{
    int b = blockIdx.x, u = threadIdx.x;
    float z  = sigm(g_gb1[b * NG3 + 512 + u]);
    float nn = tanh_fast(g_gb1[b * NG3 + 1024 + u]);
    g_h1b[b * HH + u] = (1.f - z) * nn;
}

// backward step 2 projection: h1b @ Wi[1][1] + b[1][1]
__global__ __launch_bounds__(128) void k_gb2(const float* __restrict__ Wi,
                                             const float* __restrict__ bv)
{
    int n = blockIdx.x * 64;
    int gate = n >> 9, cig = n & 511;
    const float* B512 = Wi + ((long)(3 * 3 + gate)) * 512 * 512 + cig;   // Wi[1][1]
    gemm_core(g_h1b, HH, B512, 512, bv + 3 * NG3 + n, g_gb2 + n, NG3);
}

__global__ void k_ewb2()
{
    int b = blockIdx.x, u = threadIdx.x;
    float z  = sigm(g_gb2[b * NG3 + 512 + u]);
    float nn = tanh_fast(g_gb2[b * NG3 + 1024 + u]);
    g_fcin[b * (2 * HH) + HH + u] = (1.f - z) * nn;
}

// final FC: out[64,512] = fcin[64,1024] @ fc_w + fc_b
__global__ __launch_bounds__(128) void k_fc(const float* __restrict__ fw,
                                            const float* __restrict__ fb,
                                            float* __restrict__ out)
{
    int n = blockIdx.x * 64;
    gemm_core(g_fcin, 2 * HH, fw + n, 2 * HH, fb + n, out + n, HH);
}

// ---------------- launch ------------------------------------------------------
extern "C" void kernel_launch(void* const* d_in, const int* in_sizes, int n_in,
                              void* d_out, int out_size)
{
    const float* x  = (const float*)d_in[0];
    const float* Wi = (const float*)d_in[1];
    const float* Wh = (const float*)d_in[2];
    const float* bv = (const float*)d_in[3];
    const float* fw = (const float*)d_in[4];
    const float* fb = (const float*)d_in[5];
    float* out = (float*)d_out;

    cudaFuncSetAttribute(k_scan, cudaFuncAttributeMaxDynamicSharedMemorySize, SCAN_SMEM);

    k_zero<<<64, 256>>>();                       // launch 1

    dim3 gp(NG3 / 64, SS);
    k_proj<<<gp, 128>>>(x, Wi, bv);              // launch 2

    k_gb1<<<NG3 / 64, 128>>>(x, Wi, bv);         // launch 3

    // forward scan at launch position 4 (ncu capture slot)
    k_scan<<<NGRID, THR, SCAN_SMEM>>>(Wi, Wh, bv);

    k_ewb1<<<BB, HH>>>();                        // launch 5
    k_gb2<<<NG3 / 64, 128>>>(Wi, bv);            // launch 6
    k_ewb2<<<BB, HH>>>();                        // launch 7
    k_fc<<<HH / 64, 128>>>(fw, fb, out);         // launch 8
}

// round 16
// speedup vs baseline: 1.4322x; 1.4322x over previous
#include <cuda_runtime.h>
#include <cuda_fp16.h>
#include <cuda_bf16.h>

// Problem constants
#define BB   64
#define SS   1024
#define II   512
#define HH   512
#define NG3  1536          // 3*H
#define NWORK 96           // 3 classes x 32 working CTAs
#define NGRID 192          // padded grid (dummies exit immediately)
#define THR  256           // 8 warps: n-split (nh = warp>>2 picks 3 of 6 nf)
#define BWORDS 12288       // B_perm fp16x2 words (48 KB)
#define SCAN_SMEM 131072   // request > 113KB -> 1 CTA/SM guaranteed

// ---------------- static device scratch --------------------------------------
__device__ float g_xs1[(long)SS * BB * NG3];     // layer-1 input projections
__device__ unsigned g_h1p16[16][BB * HH / 2];    // fp16x2 h1 ring (fragment-perm)
__device__ unsigned g_h2p16[2][BB * HH / 2];     // fp16x2 h2 pingpong (perm)
__device__ float g_xg2r[16][BB * NG3];           // layer-2 input projection ring
__device__ float g_gb1[BB * NG3];
__device__ float g_gb2[BB * NG3];
__device__ float g_h1b[BB * HH];
__device__ float g_fcin[BB * 2 * HH];            // [b][fwd H | bwd H]

__device__ unsigned g_flg[3][32];                // per-class per-CTA progress flags

// ---------------- helpers ----------------------------------------------------
__device__ __forceinline__ unsigned f2tf(float f) {
    unsigned u;
    asm("cvt.rna.tf32.f32 %0, %1;" : "=r"(u) : "f"(f));
    return u;
}

__device__ __forceinline__ unsigned packh2(float lo, float hi) {
    __half2 h = __floats2half2_rn(lo, hi);
    return *(unsigned*)&h;
}

// fp16 MMA: D[16x8] += A[16x16] * B[16x8], fp32 accum
__device__ __forceinline__ void mmah(float c[4], const unsigned a[4], unsigned b0, unsigned b1) {
    asm volatile(
        "mma.sync.aligned.m16n8k16.row.col.f32.f16.f16.f32 "
        "{%0,%1,%2,%3},{%4,%5,%6,%7},{%8,%9},{%0,%1,%2,%3};"
        : "+f"(c[0]), "+f"(c[1]), "+f"(c[2]), "+f"(c[3])
        : "r"(a[0]), "r"(a[1]), "r"(a[2]), "r"(a[3]), "r"(b0), "r"(b1));
}

// tf32 MMA (non-scan kernels)
__device__ __forceinline__ void mma8(float c[4], const unsigned a[4], unsigned b0, unsigned b1) {
    asm volatile(
        "mma.sync.aligned.m16n8k8.row.col.f32.tf32.tf32.f32 "
        "{%0,%1,%2,%3},{%4,%5,%6,%7},{%8,%9},{%0,%1,%2,%3};"
        : "+f"(c[0]), "+f"(c[1]), "+f"(c[2]), "+f"(c[3])
        : "r"(a[0]), "r"(a[1]), "r"(a[2]), "r"(a[3]), "r"(b0), "r"(b1));
}

__device__ __forceinline__ float sigm(float v) { return 1.f / (1.f + __expf(-v)); }
__device__ __forceinline__ float tanh_fast(float v) {
    return 1.f - 2.f / (1.f + __expf(2.f * v));
}

// fused dual-array wait: one poll round checks fA[lane]>=tA (and fB[lane]>=tB)
__device__ __forceinline__ void wait_fused(const unsigned* fA, unsigned tA,
                                           const unsigned* fB, unsigned tB, bool useB) {
    if (threadIdx.x < 32) {
        bool done = false;
        while (!done) {
            unsigned v;
            asm volatile("ld.acquire.gpu.u32 %0, [%1];"
                         : "=r"(v) : "l"(fA + threadIdx.x) : "memory");
            bool ok = (v >= tA);
            if (useB) {
                unsigned w;
                asm volatile("ld.acquire.gpu.u32 %0, [%1];"
                             : "=r"(w) : "l"(fB + threadIdx.x) : "memory");
                ok = ok && (w >= tB);
            }
            done = __all_sync(0xFFFFFFFFu, ok);
        }
    }
    __syncthreads();
}

// B2 wait: own class (lane-indexed) + single xg2 producer flag, one round
__device__ __forceinline__ void wait_b2(const unsigned* fown, unsigned town,
                                        const unsigned* fxg, unsigned txg) {
    if (threadIdx.x < 32) {
        bool done = false;
        while (!done) {
            unsigned v, w;
            asm volatile("ld.acquire.gpu.u32 %0, [%1];"
                         : "=r"(v) : "l"(fown + threadIdx.x) : "memory");
            asm volatile("ld.acquire.gpu.u32 %0, [%1];"
                         : "=r"(w) : "l"(fxg) : "memory");
            done = __all_sync(0xFFFFFFFFu, (v >= town) && (w >= txg));
        }
    }
    __syncthreads();
}

// publish own progress flag (release)
__device__ __forceinline__ void publish(unsigned* flag, unsigned target) {
    __syncthreads();
    if (threadIdx.x == 0) {
        __threadfence();
        asm volatile("st.release.gpu.u32 [%0], %1;" :: "l"(flag), "r"(target) : "memory");
    }
}

// ---------------- 64x64 TF32 GEMM core (non-scan kernels) --------------------
__device__ __forceinline__ void gemm_core(const float* __restrict__ A, long lda,
                                          const float* __restrict__ B512, int K,
                                          const float* __restrict__ bias,
                                          float* __restrict__ C, int ldc)
{
    __shared__ unsigned As[64][33];
    __shared__ unsigned Bs[32][65];

    const int tid  = threadIdx.x;
    const int lane = tid & 31;
    const int warp = tid >> 5;
    const int wm = warp >> 1, wn = warp & 1;
    const int g = lane >> 2, t = lane & 3;

    float acc[2][4][4];
#pragma unroll
    for (int a = 0; a < 2; a++)
#pragma unroll
        for (int b = 0; b < 4; b++)
#pragma unroll
            for (int c = 0; c < 4; c++) acc[a][b][c] = 0.f;

    float4 ra[4], rbv[4];
#pragma unroll
    for (int i = 0; i < 4; i++) {
        int f = tid + i * 128;
        ra[i]  = *(const float4*)(A + (long)(f >> 3) * lda + ((f & 7) << 2));
        rbv[i] = *(const float4*)(B512 + (long)(f >> 4) * 512 + ((f & 15) << 2));
    }

    for (int kc = 0; kc < K; kc += 32) {
#pragma unroll
        for (int i = 0; i < 4; i++) {
            int f = tid + i * 128;
            int r = f >> 3, cc = (f & 7) << 2;
            As[r][cc + 0] = f2tf(ra[i].x);
            As[r][cc + 1] = f2tf(ra[i].y);
            As[r][cc + 2] = f2tf(ra[i].z);
            As[r][cc + 3] = f2tf(ra[i].w);
            int bk = f >> 4, bc = (f & 15) << 2;
            Bs[bk][bc + 0] = f2tf(rbv[i].x);
            Bs[bk][bc + 1] = f2tf(rbv[i].y);
            Bs[bk][bc + 2] = f2tf(rbv[i].z);
            Bs[bk][bc + 3] = f2tf(rbv[i].w);
        }
        __syncthreads();

        if (kc + 32 < K) {
#pragma unroll
            for (int i = 0; i < 4; i++) {
                int f = tid + i * 128;
                ra[i]  = *(const float4*)(A + (long)(f >> 3) * lda + (kc + 32) + ((f & 7) << 2));
                rbv[i] = *(const float4*)(B512 + (long)(kc + 32 + (f >> 4)) * 512 + ((f & 15) << 2));
            }
        }

#pragma unroll
        for (int ks = 0; ks < 4; ks++) {
            int kb = ks * 8;
            unsigned afr[2][4];
#pragma unroll
            for (int mf = 0; mf < 2; mf++) {
                int rb_ = wm * 32 + mf * 16;
                afr[mf][0] = As[rb_ + g][kb + t];
                afr[mf][1] = As[rb_ + 8 + g][kb + t];
                afr[mf][2] = As[rb_ + g][kb + 4 + t];
                afr[mf][3] = As[rb_ + 8 + g][kb + 4 + t];
            }
#pragma unroll
            for (int nf = 0; nf < 4; nf++) {
                int cb = wn * 32 + nf * 8;
                unsigned b0 = Bs[kb + t][cb + g];
                unsigned b1 = Bs[kb + 4 + t][cb + g];
                mma8(acc[0][nf], afr[0], b0, b1);
                mma8(acc[1][nf], afr[1], b0, b1);
            }
        }
        __syncthreads();
    }

#pragma unroll
    for (int mf = 0; mf < 2; mf++)
#pragma unroll
        for (int nf = 0; nf < 4; nf++) {
            int row = wm * 32 + mf * 16 + g;
            int col = wn * 32 + nf * 8 + t * 2;
            float b0v = bias ? bias[col] : 0.f;
            float b1v = bias ? bias[col + 1] : 0.f;
            C[(long)row * ldc + col]           = acc[mf][nf][0] + b0v;
            C[(long)row * ldc + col + 1]       = acc[mf][nf][1] + b1v;
            C[(long)(row + 8) * ldc + col]     = acc[mf][nf][2] + b0v;
            C[(long)(row + 8) * ldc + col + 1] = acc[mf][nf][3] + b1v;
        }
}

// ---------------- kernels -----------------------------------------------------

__global__ void k_zero() {
    long n = BB * HH / 2;
    for (long i = blockIdx.x * blockDim.x + threadIdx.x; i < n; i += (long)gridDim.x * blockDim.x) {
        g_h1p16[0][i] = 0u;
        g_h2p16[0][i] = 0u;
    }
    if (blockIdx.x == 0 && threadIdx.x < 96)
        g_flg[threadIdx.x >> 5][threadIdx.x & 31] = 0;
}

// xs1[s][b][n] = x[b][s][:] @ Wi[0][0][gate] + b[0][0]
__global__ __launch_bounds__(128) void k_proj(const float* __restrict__ x,
                                              const float* __restrict__ Wi,
                                              const float* __restrict__ bv)
{
    int n = blockIdx.x * 64;
    int s = blockIdx.y;
    int gate = n >> 9, cig = n & 511;
    const float* A = x + (long)s * II;
    const float* B512 = Wi + ((long)(0 * 3 + gate)) * 512 * 512 + cig;   // Wi[0][0]
    gemm_core(A, (long)SS * II, B512, 512, bv + n,
              g_xs1 + ((long)s * BB) * NG3 + n, NG3);
}

// ---------------- persistent scan kernel (FP16 MMA, n-split, fused waits) -----
// R14 GEMM/prefetch (depth 8, no spills) + single-round fused waits,
// 16-slot rings with slack checked every 4th iteration, B2 single-flag wait.
//   A  (0-31):  Wh1 over h1(it)   -> EW L1 -> h1(it+1) ring[16]
//   B1 (32-63): Wi2 over h1(it+1) -> xg2[it] ring[16]
//   B2 (64-95): Wh2 over h2(it) + EW L2 (xg2[it]) -> h2(it+1)
__global__ void __launch_bounds__(THR, 1) k_scan(const float* __restrict__ Wi,
                                                 const float* __restrict__ Wh,
                                                 const float* __restrict__ bv)
{
    extern __shared__ unsigned smemu[];
    unsigned* Bsm = smemu;               // B_perm fp16x2 (48 KB)

    const int tid  = threadIdx.x;
    const int lane = tid & 31;
    const int warp = tid >> 5;           // 0..7
    const int wg   = warp & 3;           // row group
    const int nh   = warp >> 2;          // nf half == u half
    const int g = lane >> 2, t = lane & 3;
    const int ct = blockIdx.x;
    if (ct >= NWORK) return;             // grid padding
    const int cls = ct >> 5;             // 0=A, 1=B1, 2=B2
    const int ci  = ct & 31;
    const int u0  = ci * 16;

    // ---- one-time weight stage into B_perm (fp16x2); nf = uh*3 + gate ----
    const float* Wbase = (cls == 0) ? Wh : (cls == 1) ? (Wi + 6L * 262144)
                                                      : (Wh + 6L * 262144);
    for (int widx = tid; widx < BWORDS; widx += THR) {
        int reg = widx & 1;
        int lane2 = (widx >> 1) & 31;
        int m = widx >> 6;               // c*6 + nf
        int nf = m % 6, c = m / 6;
        int g2 = lane2 >> 2, t2 = lane2 & 3;
        int kk = c * 16 + reg * 8 + t2 * 2;
        int gate = nf % 3, uh = nf / 3;
        int col = u0 + uh * 8 + g2;
        const float* Wg = Wbase + (long)gate * 262144;
        Bsm[widx] = packh2(Wg[(long)kk * 512 + col], Wg[(long)(kk + 1) * 512 + col]);
    }

    // layer-2 bias prefetch (b[1][0]) for B2, this warp's u-half
    const float* b2 = bv + 2 * NG3;
    float b2r[2], b2z[2], b2n[2];
    if (cls == 2) {
#pragma unroll
        for (int jl = 0; jl < 2; jl++) {
            int u = u0 + nh * 8 + t * 2 + jl;
            b2r[jl] = __ldg(b2 + u);
            b2z[jl] = __ldg(b2 + 512 + u);
            b2n[jl] = __ldg(b2 + 1024 + u);
        }
    }

    float hreg[2][2];                    // own h cells [j2][jl] (this warp's u-half)
#pragma unroll
    for (int a = 0; a < 2; a++)
#pragma unroll
        for (int b = 0; b < 2; b++) hreg[a][b] = 0.f;

    __syncthreads();                     // B_perm ready

    for (int it = 0; it < SS; it++) {
        // ---- fused top waits (one poll round; slack checked every 4th it) ----
        const bool chk = (it >= 8) && ((it & 3) == 0);
        const unsigned* hp;
        if (cls == 0) {
            wait_fused(g_flg[0], (unsigned)it, g_flg[1], (unsigned)(it - 7), chk);
            hp = g_h1p16[it & 15];
        } else if (cls == 1) {
            wait_fused(g_flg[0], (unsigned)(it + 1), g_flg[2], (unsigned)(it - 7), chk);
            hp = g_h1p16[(it + 1) & 15];
        } else {
            wait_b2(g_flg[2], (unsigned)it, &g_flg[1][ci], (unsigned)(it + 1));
            hp = g_h2p16[it & 1];
        }

        // EW operand prefetch (this warp's u-half; independent of GEMM)
        float pf_x[2][2][3];             // [j2][jl][gate]
        if (cls == 0) {
#pragma unroll
            for (int j2 = 0; j2 < 2; j2++) {
                int b = wg * 16 + g + 8 * j2;
                const float* xs = g_xs1 + ((long)it * BB + b) * NG3;
#pragma unroll
                for (int jl = 0; jl < 2; jl++) {
                    int u = u0 + nh * 8 + t * 2 + jl;
                    pf_x[j2][jl][0] = __ldcg(xs + u);
                    pf_x[j2][jl][1] = __ldcg(xs + 512 + u);
                    pf_x[j2][jl][2] = __ldcg(xs + 1024 + u);
                }
            }
        } else if (cls == 2) {
            const float* xg = g_xg2r[it & 15];
#pragma unroll
            for (int j2 = 0; j2 < 2; j2++) {
                int b = wg * 16 + g + 8 * j2;
#pragma unroll
                for (int jl = 0; jl < 2; jl++) {
                    int u = u0 + nh * 8 + t * 2 + jl;
                    pf_x[j2][jl][0] = __ldcg(xg + b * NG3 + u);
                    pf_x[j2][jl][1] = __ldcg(xg + b * NG3 + 512 + u);
                    pf_x[j2][jl][2] = __ldcg(xg + b * NG3 + 1024 + u);
                }
            }
        }

        // ---- GEMM: 32 k16-chunks, 3 nf frags, A from L2, 8-deep prefetch ----
        const uint4* gA = (const uint4*)hp + wg * 32 + lane;
        float acc[3][4];
#pragma unroll
        for (int f = 0; f < 3; f++)
#pragma unroll
            for (int c = 0; c < 4; c++) acc[f][c] = 0.f;

        uint4 areg[8];
#pragma unroll
        for (int j = 0; j < 8; j++) areg[j] = __ldcg(gA + j * 128);

#pragma unroll 8
        for (int c = 0; c < 32; c++) {
            unsigned a[4] = {areg[c & 7].x, areg[c & 7].y,
                             areg[c & 7].z, areg[c & 7].w};
            if (c + 8 < 32) areg[c & 7] = __ldcg(gA + (c + 8) * 128);
            const unsigned* Bp = Bsm + c * 384 + (nh * 3) * 64 + lane * 2;
#pragma unroll
            for (int f = 0; f < 3; f++) {
                uint2 bb = *(const uint2*)(Bp + f * 64);
                mmah(acc[f], a, bb.x, bb.y);
            }
        }

        // ---- class-specific epilogue (this warp's u-half) ----
        if (cls == 0) {
            unsigned* hout = g_h1p16[(it + 1) & 15];
            unsigned base = ((unsigned)(ci * 4 + wg) * 32 + lane) * 4;
#pragma unroll
            for (int j2 = 0; j2 < 2; j2++) {
                float v2[2];
#pragma unroll
                for (int jl = 0; jl < 2; jl++) {
                    int c = j2 * 2 + jl;
                    float r  = sigm(pf_x[j2][jl][0] + acc[0][c]);
                    float z  = sigm(pf_x[j2][jl][1] + acc[1][c]);
                    float nn = tanh_fast(pf_x[j2][jl][2] + r * acc[2][c]);
                    float v  = (1.f - z) * nn + z * hreg[j2][jl];
                    hreg[j2][jl] = v;
                    v2[jl] = v;
                }
                __stcg(&hout[base + j2 + 2 * nh], packh2(v2[0], v2[1]));
            }
        } else if (cls == 1) {
            float* xg = g_xg2r[it & 15];
#pragma unroll
            for (int gate = 0; gate < 3; gate++)
#pragma unroll
                for (int j2 = 0; j2 < 2; j2++) {
                    int b = wg * 16 + g + 8 * j2;
                    float2 val = make_float2(acc[gate][j2 * 2], acc[gate][j2 * 2 + 1]);
                    __stcg((float2*)(xg + b * NG3 + gate * 512 + u0 + nh * 8 + t * 2), val);
                }
        } else {
            unsigned* hout = g_h2p16[(it + 1) & 1];
            unsigned base = ((unsigned)(ci * 4 + wg) * 32 + lane) * 4;
#pragma unroll
            for (int j2 = 0; j2 < 2; j2++) {
                int b = wg * 16 + g + 8 * j2;
                float v2[2];
#pragma unroll
                for (int jl = 0; jl < 2; jl++) {
                    int u = u0 + nh * 8 + t * 2 + jl;
                    int c = j2 * 2 + jl;
                    float xr = pf_x[j2][jl][0] + b2r[jl];
                    float xz = pf_x[j2][jl][1] + b2z[jl];
                    float xn = pf_x[j2][jl][2] + b2n[jl];
                    float r2 = sigm(xr + acc[0][c]);
                    float z2 = sigm(xz + acc[1][c]);
                    float n2 = tanh_fast(xn + r2 * acc[2][c]);
                    float v  = (1.f - z2) * n2 + z2 * hreg[j2][jl];
                    hreg[j2][jl] = v;
                    v2[jl] = v;
                    if (it == SS - 1) __stcg(&g_fcin[b * (2 * HH) + u], v);
                }
                __stcg(&hout[base + j2 + 2 * nh], packh2(v2[0], v2[1]));
            }
        }

        publish(&g_flg[cls][ci], (unsigned)(it + 1));
    }
}

// backward step 1 projection: x[:,1023,:] @ Wi[0][1] + b[0][1]
__global__ __launch_bounds__(128) void k_gb1(const float* __restrict__ x,
                                             const float* __restrict__ Wi,
                                             const float* __restrict__ bv)
{
    int n = blockIdx.x * 64;
    int gate = n >> 9, cig = n & 511;
    const float* A = x + (long)(SS - 1) * II;
    const float* B512 = Wi + ((long)(1 * 3 + gate)) * 512 * 512 + cig;   // Wi[0][1]
    gemm_core(A, (long)SS * II, B512, 512, bv + 1 * NG3 + n, g_gb1 + n, NG3);
}

__global__ void k_ewb1()
{
    int b = blockIdx.x, u = threadIdx.x;
    float z  = sigm(g_gb1[b * NG3 + 512 + u]);
    float nn = tanh_fast(g_gb1[b * NG3 + 1024 + u]);
    g_h1b[b * HH + u] = (1.f - z) * nn;
}

// backward step 2 projection: h1b @ Wi[1][1] + b[1][1]
__global__ __launch_bounds__(128) void k_gb2(const float* __restrict__ Wi,
                                             const float* __restrict__ bv)
{
    int n = blockIdx.x * 64;
    int gate = n >> 9, cig = n & 511;
    const float* B512 = Wi + ((long)(3 * 3 + gate)) * 512 * 512 + cig;   // Wi[1][1]
    gemm_core(g_h1b, HH, B512, 512, bv + 3 * NG3 + n, g_gb2 + n, NG3);
}

__global__ void k_ewb2()
{
    int b = blockIdx.x, u = threadIdx.x;
    float z  = sigm(g_gb2[b * NG3 + 512 + u]);
    float nn = tanh_fast(g_gb2[b * NG3 + 1024 + u]);
    g_fcin[b * (2 * HH) + HH + u] = (1.f - z) * nn;
}

// final FC: out[64,512] = fcin[64,1024] @ fc_w + fc_b
__global__ __launch_bounds__(128) void k_fc(const float* __restrict__ fw,
                                            const float* __restrict__ fb,
                                            float* __restrict__ out)
{
    int n = blockIdx.x * 64;
    gemm_core(g_fcin, 2 * HH, fw + n, 2 * HH, fb + n, out + n, HH);
}

// ---------------- launch ------------------------------------------------------
extern "C" void kernel_launch(void* const* d_in, const int* in_sizes, int n_in,
                              void* d_out, int out_size)
{
    const float* x  = (const float*)d_in[0];
    const float* Wi = (const float*)d_in[1];
    const float* Wh = (const float*)d_in[2];
    const float* bv = (const float*)d_in[3];
    const float* fw = (const float*)d_in[4];
    const float* fb = (const float*)d_in[5];
    float* out = (float*)d_out;

    cudaFuncSetAttribute(k_scan, cudaFuncAttributeMaxDynamicSharedMemorySize, SCAN_SMEM);

    k_zero<<<64, 256>>>();                       // launch 1

    dim3 gp(NG3 / 64, SS);
    k_proj<<<gp, 128>>>(x, Wi, bv);              // launch 2

    k_gb1<<<NG3 / 64, 128>>>(x, Wi, bv);         // launch 3

    // forward scan at launch position 4 (ncu capture slot)
    k_scan<<<NGRID, THR, SCAN_SMEM>>>(Wi, Wh, bv);

    k_ewb1<<<BB, HH>>>();                        // launch 5
    k_gb2<<<NG3 / 64, 128>>>(Wi, bv);            // launch 6
    k_ewb2<<<BB, HH>>>();                        // launch 7
    k_fc<<<HH / 64, 128>>>(fw, fb, out);         // launch 8
}